// round 13
// baseline (speedup 1.0000x reference)
#include <cuda_runtime.h>
#include <math.h>
#include <stdint.h>

// Problem constants
#define BB 8
#define TT 256
#define DD 256      // q_size / feature dim
#define HH 128
#define WW 128
#define CS 512      // c_size
#define MM (BB*TT)  // 2048 rows
#define RR 9
#define CC 9
#define KK 81       // R*C
#define ROWS 129    // H+1
#define COLS 129    // W+1
#define QTOT (8LL*256LL*16384LL)   // total floats in q

// Scratch (device globals; no allocation allowed)
__device__ float g_h[MM * 256];   // pre-tanh hidden (W_p path)
__device__ float g_u[MM * 256];   // u = c_t @ W_a

// ---------------------------------------------------------------------------
// Kernel 1: fused GEMM, scalar FFMA 8x4 micro-tile, BM=64 BN=64 BK=16,
// 128 threads, transposed A tile (LDS.128 frags), double-buffered,
// software-pipelined LDG.  (R10 version — best measured: 40.5us)
// ---------------------------------------------------------------------------
__global__ __launch_bounds__(128)
void gemm_kernel(const float* __restrict__ A,   // c_t (2048,512)
                 const float* __restrict__ Wp,  // (256,512)
                 const float* __restrict__ Wa)  // (512,256)
{
    __shared__ float As[2][16][68];   // [buf][k][m], stride 68 -> 16B aligned
    __shared__ float Bs[2][16][64];   // [buf][k][n]

    const int m0 = blockIdx.x * 64;
    const int n0 = blockIdx.y * 64;
    const bool is_u = (n0 >= 256);
    const int tid = threadIdx.x;
    const int tx = tid & 15;        // 0..15 -> n (4 cols each)
    const int ty = tid >> 4;        // 0..7  -> m (8 rows each)

    const int a_row = tid >> 2;             // 0..31
    const int a_kk  = (tid & 3) << 2;       // 0,4,8,12
    const int bp_n  = tid >> 2;
    const int bp_kk = (tid & 3) << 2;
    const int ba_k  = tid >> 4;             // 0..7 (+8 for second)
    const int ba_nn = (tid & 15) << 2;

    float acc[8][4];
#pragma unroll
    for (int i = 0; i < 8; i++)
#pragma unroll
        for (int j = 0; j < 4; j++) acc[i][j] = 0.f;

    float4 ra[2], rb[2];

    auto ldg_tile = [&](int k0) {
#pragma unroll
        for (int s = 0; s < 2; s++)
            ra[s] = *(const float4*)(A + (size_t)(m0 + a_row + s * 32) * CS + k0 + a_kk);
        if (!is_u) {
#pragma unroll
            for (int s = 0; s < 2; s++)
                rb[s] = *(const float4*)(Wp + (size_t)(n0 + bp_n + s * 32) * CS + k0 + bp_kk);
        } else {
#pragma unroll
            for (int s = 0; s < 2; s++)
                rb[s] = *(const float4*)(Wa + (size_t)(k0 + ba_k + s * 8) * 256 + (n0 - 256) + ba_nn);
        }
    };

    auto sts_tile = [&](int bf) {
#pragma unroll
        for (int s = 0; s < 2; s++) {
            int row = a_row + s * 32;
            As[bf][a_kk + 0][row] = ra[s].x;
            As[bf][a_kk + 1][row] = ra[s].y;
            As[bf][a_kk + 2][row] = ra[s].z;
            As[bf][a_kk + 3][row] = ra[s].w;
        }
        if (!is_u) {
#pragma unroll
            for (int s = 0; s < 2; s++) {
                int n = bp_n + s * 32;
                Bs[bf][bp_kk + 0][n] = rb[s].x;
                Bs[bf][bp_kk + 1][n] = rb[s].y;
                Bs[bf][bp_kk + 2][n] = rb[s].z;
                Bs[bf][bp_kk + 3][n] = rb[s].w;
            }
        } else {
#pragma unroll
            for (int s = 0; s < 2; s++)
                *(float4*)&Bs[bf][ba_k + s * 8][ba_nn] = rb[s];
        }
    };

    ldg_tile(0);
    sts_tile(0);
    __syncthreads();

    int buf = 0;
    for (int t = 0; t < 32; t++) {
        const bool more = (t < 31);
        if (more) ldg_tile((t + 1) * 16);
#pragma unroll
        for (int k = 0; k < 16; k++) {
            float4 a4 = *(const float4*)&As[buf][k][ty * 8];
            float4 a5 = *(const float4*)&As[buf][k][ty * 8 + 4];
            float4 b4 = *(const float4*)&Bs[buf][k][tx * 4];
            float a[8] = {a4.x, a4.y, a4.z, a4.w, a5.x, a5.y, a5.z, a5.w};
            float b[4] = {b4.x, b4.y, b4.z, b4.w};
#pragma unroll
            for (int i = 0; i < 8; i++)
#pragma unroll
                for (int j = 0; j < 4; j++)
                    acc[i][j] = fmaf(a[i], b[j], acc[i][j]);
        }
        if (more) { sts_tile(buf ^ 1); __syncthreads(); }
        buf ^= 1;
    }

#pragma unroll
    for (int i = 0; i < 8; i++) {
        int mrow = m0 + ty * 8 + i;
        float4 v = make_float4(acc[i][0], acc[i][1], acc[i][2], acc[i][3]);
        if (!is_u) *(float4*)&g_h[(size_t)mrow * 256 + n0 + tx * 4] = v;
        else       *(float4*)&g_u[(size_t)mrow * 256 + (n0 - 256) + tx * 4] = v;
    }
}

// ---------------------------------------------------------------------------
// Register gather: thread owns feature d; loads its 9 window rows as 3
// aligned float4s (48B span) and keeps the 9 needed values per row in a
// register array sreg[81]. Invalid slots hold finite garbage (masked later).
// ---------------------------------------------------------------------------
template<int OFF>
__device__ __forceinline__ void gather_rows(const float* __restrict__ q,
                                            long long gbase,   // b*4194304 + d*16384 + a0
                                            const int* __restrict__ sri,
                                            float (&sreg)[KK])
{
#pragma unroll
    for (int i = 0; i < 9; i++) {
        int rv = sri[i];
        float f[12];
        if (rv > 0) {
            long long g = gbase + (long long)(rv - 1) * 128;
            if (g >= 0 && g + 12 <= QTOT) {
                float4 v0 = __ldg((const float4*)(q + g));
                float4 v1 = __ldg((const float4*)(q + g + 4));
                float4 v2 = __ldg((const float4*)(q + g + 8));
                f[0] = v0.x; f[1] = v0.y; f[2]  = v0.z; f[3]  = v0.w;
                f[4] = v1.x; f[5] = v1.y; f[6]  = v1.z; f[7]  = v1.w;
                f[8] = v2.x; f[9] = v2.y; f[10] = v2.z; f[11] = v2.w;
            } else {
                // Rare buffer-edge fallback
#pragma unroll
                for (int x = 0; x < 12; x++) {
                    long long gg = g + x;
                    f[x] = (gg >= 0 && gg < QTOT) ? __ldg(q + gg) : 0.f;
                }
            }
        } else {
#pragma unroll
            for (int x = 0; x < 12; x++) f[x] = 0.f;
        }
#pragma unroll
        for (int j = 0; j < 9; j++) sreg[i * 9 + j] = f[OFF + j];
    }
}

// ---------------------------------------------------------------------------
// Kernel 2: local attention, register-resident window. One CTA per (b,t),
// 256 threads, thread d = tid. Score via warp shuffle-reduction (no smem
// window, no score LDS). Inlined p_t.
// ---------------------------------------------------------------------------
__global__ __launch_bounds__(256)
void attn_kernel(const float* __restrict__ q,
                 const float* __restrict__ Vp,   // (2,256)
                 float* __restrict__ out)
{
    __shared__ float spart[8 * KK];        // per-warp score partials
    __shared__ float sp0[256], sp1[256];   // p_t partial products
    __shared__ float spp[2];               // p0, p1
    __shared__ float sa[KK];
    __shared__ float sw[KK];
    __shared__ float sred[2];
    __shared__ int   sri[RR], sci[CC];
    __shared__ float srex[RR], scex[CC];
    __shared__ int   scb;                  // rint(p1)

    const int t = blockIdx.x;
    const int b = blockIdx.y;
    const int m = b * TT + t;
    const int tid = threadIdx.x;
    const int lane = tid & 31;
    const int wid = tid >> 5;

    // own u value + p_t partials (p_t = 128*sigmoid(tanh(h) @ Vp^T))
    const float su_d = g_u[(size_t)m * 256 + tid];
    {
        float hv = tanhf(g_h[(size_t)m * 256 + tid]);
        sp0[tid] = hv * Vp[tid];
        sp1[tid] = hv * Vp[256 + tid];
    }
    __syncthreads();

    // two warps reduce the two 256-sums
    if (tid < 64) {
        const float* sp = (tid < 32) ? sp0 : sp1;
        float v = 0.f;
#pragma unroll
        for (int j = 0; j < 8; j++) v += sp[lane + 32 * j];
#pragma unroll
        for (int off = 16; off > 0; off >>= 1)
            v += __shfl_xor_sync(0xffffffffu, v, off);
        if (lane == 0) spp[tid >> 5] = 128.f / (1.f + expf(-v));
    }
    __syncthreads();

    const float p0 = spp[0];
    const float p1 = spp[1];

    // indices + gaussian terms
    if (tid < RR) {
        int cr = (int)rintf(p0);
        int v = cr + tid - 3;                  // round(p0) + off + 1, off = tid-4
        v = min(max(v, 0), ROWS);
        if (v == ROWS) v = 0;
        sri[tid] = v;
        float rr = (float)max(v - 1, 0);
        float d = (rr - p0) * 0.25f;
        srex[tid] = -2.f * d * d;
    } else if (tid < RR + CC) {
        int i = tid - RR;
        int cc = (int)rintf(p1);
        if (i == 0) scb = cc;
        int v = cc + i - 3;
        v = min(max(v, 0), COLS);
        if (v == COLS) v = 0;
        sci[i] = v;
        float ccf = (float)max(v - 1, 0);
        float d = (ccf - p1) * 0.25f;
        scex[i] = -2.f * d * d;
    }
    __syncthreads();

    // Gather window into registers: sreg[k], k = i*9 + j, d = tid
    float sreg[KK];
    {
        const int cb = scb;
        const int a0 = (cb - 4) & ~3;          // aligned col start (may be -4)
        const int off = (cb - 4) & 3;          // uniform 0..3
        const long long gbase = (long long)b * 4194304LL
                              + (long long)tid * 16384LL + a0;
        switch (off) {
            case 0: gather_rows<0>(q, gbase, sri, sreg); break;
            case 1: gather_rows<1>(q, gbase, sri, sreg); break;
            case 2: gather_rows<2>(q, gbase, sri, sreg); break;
            default: gather_rows<3>(q, gbase, sri, sreg); break;
        }
    }

    // Scores: a[k] = sum_d su[d]*s[d][k]; warp butterfly over the 32 d's,
    // lane 0 stores the warp partial.
#pragma unroll
    for (int k = 0; k < KK; k++) {
        float v = su_d * sreg[k];
#pragma unroll
        for (int off = 16; off > 0; off >>= 1)
            v += __shfl_xor_sync(0xffffffffu, v, off);
        if (lane == 0) spart[wid * KK + k] = v;
    }
    __syncthreads();

    if (tid < KK) {
        float a = 0.f;
#pragma unroll
        for (int w = 0; w < 8; w++) a += spart[w * KK + tid];
        int i = tid / CC, j = tid - i * CC;
        bool valid = (sri[i] > 0) && (sci[j] > 0);
        sa[tid] = valid ? a : -INFINITY;
    }
    __syncthreads();

    // max
    if (tid < 32) {
        float mx = -INFINITY;
        for (int k = tid; k < KK; k += 32) mx = fmaxf(mx, sa[k]);
#pragma unroll
        for (int off = 16; off > 0; off >>= 1)
            mx = fmaxf(mx, __shfl_xor_sync(0xffffffffu, mx, off));
        if (tid == 0) sred[0] = mx;
    }
    __syncthreads();
    const float mx = sred[0];
    if (tid < KK) sa[tid] = expf(sa[tid] - mx);
    __syncthreads();
    if (tid < 32) {
        float sm = 0.f;
        for (int k = tid; k < KK; k += 32) sm += sa[k];
#pragma unroll
        for (int off = 16; off > 0; off >>= 1)
            sm += __shfl_xor_sync(0xffffffffu, sm, off);
        if (tid == 0) sred[1] = sm;
    }
    __syncthreads();
    const float inv = 1.f / sred[1];
    if (tid < KK) {
        int i = tid / CC, j = tid - i * CC;
        float g = expf(srex[i] + scex[j]);
        sw[tid] = sa[tid] * inv * g;
    }
    __syncthreads();

    // Output: out[m][d] = sum_k w[k] * s[d][k]  (window still in registers)
    float o0 = 0.f, o1 = 0.f, o2 = 0.f, o3 = 0.f;
#pragma unroll
    for (int k = 0; k < 80; k += 4) {
        o0 = fmaf(sw[k + 0], sreg[k + 0], o0);
        o1 = fmaf(sw[k + 1], sreg[k + 1], o1);
        o2 = fmaf(sw[k + 2], sreg[k + 2], o2);
        o3 = fmaf(sw[k + 3], sreg[k + 3], o3);
    }
    o0 = fmaf(sw[80], sreg[80], o0);
    out[(size_t)m * DD + tid] = (o0 + o1) + (o2 + o3);
}

// ---------------------------------------------------------------------------
extern "C" void kernel_launch(void* const* d_in, const int* in_sizes, int n_in,
                              void* d_out, int out_size)
{
    const float* q   = (const float*)d_in[0];   // (8,256,128,128)
    const float* c_t = (const float*)d_in[1];   // (8,256,512)
    const float* W_a = (const float*)d_in[2];   // (512,256)
    const float* W_p = (const float*)d_in[3];   // (256,512)
    const float* V_p = (const float*)d_in[4];   // (2,256)
    float* out = (float*)d_out;                 // (8,256,256)

    // Phase 1: projections (8x4 micro-tile scalar GEMM)
    gemm_kernel<<<dim3(MM / 64, 512 / 64), 128>>>(c_t, W_p, W_a);
    // Phase 2: attention, register-resident window
    attn_kernel<<<dim3(TT, BB), 256>>>(q, V_p, out);
}